// round 3
// baseline (speedup 1.0000x reference)
#include <cuda_runtime.h>

// Problem constants
#define D     768
#define T     8192
#define NREF  16384
#define C     96
#define KSEL  4

// GEMM tiling
#define TM    128
#define TN    128
#define KB    16
#define NSPLIT 2
#define CAND  64          // candidates per token per split (16 tx-threads * 4)

#define NEG_INF (-3.402823466e38f)

// ---- scratch (static device globals; no allocations allowed) ----
__device__ float g_inv_rnorm[NREF];                 // 64 KB
__device__ float g_P[C * NREF];                     // 6.3 MB : P = W @ lut
__device__ float g_cand_val[NSPLIT * T * CAND];     // 4 MB
__device__ int   g_cand_idx[NSPLIT * T * CAND];     // 4 MB

// ============================================================
// Kernel 1: inverse L2 norm of each reference column of lut [D, NREF]
// ============================================================
__global__ void norm_kernel(const float* __restrict__ lut) {
    int n = blockIdx.x * blockDim.x + threadIdx.x;
    if (n >= NREF) return;
    float s = 0.f;
#pragma unroll 8
    for (int d = 0; d < D; ++d) {
        float v = lut[d * NREF + n];
        s = fmaf(v, v, s);
    }
    g_inv_rnorm[n] = 1.0f / sqrtf(s);
}

// ============================================================
// Kernel 2: P[c][n] = sum_d W[c][d] * lut[d][n]   (96 x 16384 x 768)
// grid (NREF/128, C/4), block 128. Each thread: 1 column n, 4 channels.
// ============================================================
__global__ void proj_lut_kernel(const float* __restrict__ lut,
                                const float* __restrict__ w) {
    int n  = blockIdx.x * 128 + threadIdx.x;
    int c0 = blockIdx.y * 4;
    const float* w0 = w + (c0 + 0) * D;
    const float* w1 = w + (c0 + 1) * D;
    const float* w2 = w + (c0 + 2) * D;
    const float* w3 = w + (c0 + 3) * D;
    float a0 = 0.f, a1 = 0.f, a2 = 0.f, a3 = 0.f;
#pragma unroll 4
    for (int d = 0; d < D; ++d) {
        float l = lut[d * NREF + n];
        a0 = fmaf(w0[d], l, a0);
        a1 = fmaf(w1[d], l, a1);
        a2 = fmaf(w2[d], l, a2);
        a3 = fmaf(w3[d], l, a3);
    }
    g_P[(c0 + 0) * NREF + n] = a0;
    g_P[(c0 + 1) * NREF + n] = a1;
    g_P[(c0 + 2) * NREF + n] = a2;
    g_P[(c0 + 3) * NREF + n] = a3;
}

// ============================================================
// Kernel 3: fused GEMM + running top-4.
// score[t,n] = (sum_d x[d,t]*lut[d,n]) * inv_rnorm[n]
// grid: (NSPLIT, T/TM), block 256 (16x16), per-thread 8x8 C-tile.
// Per thread keeps top-4 per owned row across all N-tiles of its split;
// 64 candidates/token/split written to global for the merge kernel.
// ============================================================
__device__ __forceinline__ void insert4(float* v, int* ix, float s, int n) {
    if (s > v[3]) {
        if (s > v[0]) {
            v[3] = v[2]; ix[3] = ix[2];
            v[2] = v[1]; ix[2] = ix[1];
            v[1] = v[0]; ix[1] = ix[0];
            v[0] = s;    ix[0] = n;
        } else if (s > v[1]) {
            v[3] = v[2]; ix[3] = ix[2];
            v[2] = v[1]; ix[2] = ix[1];
            v[1] = s;    ix[1] = n;
        } else if (s > v[2]) {
            v[3] = v[2]; ix[3] = ix[2];
            v[2] = s;    ix[2] = n;
        } else {
            v[3] = s;    ix[3] = n;
        }
    }
}

__global__ __launch_bounds__(256, 1)
void match_kernel(const float* __restrict__ x, const float* __restrict__ lut) {
    __shared__ float As[KB][TM];
    __shared__ float Bs[KB][TN];
    __shared__ float Sn[TN];

    const int tid = threadIdx.x;
    const int tx  = tid & 15;
    const int ty  = tid >> 4;
    const int t0  = blockIdx.y * TM;
    const int nbeg = blockIdx.x * (NREF / NSPLIT);

    float topv[8][4];
    int   topi[8][4];
#pragma unroll
    for (int i = 0; i < 8; ++i)
#pragma unroll
        for (int j = 0; j < 4; ++j) { topv[i][j] = NEG_INF; topi[i][j] = 0; }

    const int NT = (NREF / NSPLIT) / TN;   // 64 n-tiles
    for (int nt = 0; nt < NT; ++nt) {
        const int n0 = nbeg + nt * TN;

        float acc[8][8];
#pragma unroll
        for (int i = 0; i < 8; ++i)
#pragma unroll
            for (int j = 0; j < 8; ++j) acc[i][j] = 0.f;

        if (tid < TN) Sn[tid] = g_inv_rnorm[n0 + tid];

        for (int kc = 0; kc < D / KB; ++kc) {
            const float* xp = x   + (kc * KB) * T    + t0;
            const float* lp = lut + (kc * KB) * NREF + n0;
#pragma unroll
            for (int i = 0; i < 8; ++i) {
                int e  = tid + i * 256;
                int kr = e >> 7;
                int cc = e & 127;
                As[kr][cc] = xp[kr * T + cc];
                Bs[kr][cc] = lp[kr * NREF + cc];
            }
            __syncthreads();

#pragma unroll
            for (int k = 0; k < KB; ++k) {
                float a[8], b[8];
                float4 v;
                v = *(const float4*)&As[k][ty * 4];
                a[0] = v.x; a[1] = v.y; a[2] = v.z; a[3] = v.w;
                v = *(const float4*)&As[k][64 + ty * 4];
                a[4] = v.x; a[5] = v.y; a[6] = v.z; a[7] = v.w;
                v = *(const float4*)&Bs[k][tx * 4];
                b[0] = v.x; b[1] = v.y; b[2] = v.z; b[3] = v.w;
                v = *(const float4*)&Bs[k][64 + tx * 4];
                b[4] = v.x; b[5] = v.y; b[6] = v.z; b[7] = v.w;
#pragma unroll
                for (int i = 0; i < 8; ++i)
#pragma unroll
                    for (int j = 0; j < 8; ++j)
                        acc[i][j] = fmaf(a[i], b[j], acc[i][j]);
            }
            __syncthreads();
        }

        // epilogue: scale by inv-norm, update running top-4 per row
        float sv[8];
        int   nn[8];
#pragma unroll
        for (int j = 0; j < 8; ++j) {
            int cl = tx * 4 + (j & 3) + ((j >> 2) * 64);
            sv[j] = Sn[cl];
            nn[j] = n0 + cl;
        }
#pragma unroll
        for (int i = 0; i < 8; ++i) {
#pragma unroll
            for (int j = 0; j < 8; ++j) {
                float s = acc[i][j] * sv[j];
                insert4(topv[i], topi[i], s, nn[j]);
            }
        }
        __syncthreads();   // protect Sn before next tile's reload
    }

    // write per-thread candidates (16 threads * 4 = 64 per token per split)
#pragma unroll
    for (int i = 0; i < 8; ++i) {
        int trow = t0 + ty * 4 + (i & 3) + ((i >> 2) * 64);
        int base = (blockIdx.x * T + trow) * CAND + tx * 4;
#pragma unroll
        for (int j = 0; j < 4; ++j) {
            g_cand_val[base + j] = topv[i][j];
            g_cand_idx[base + j] = topi[i][j];
        }
    }
}

// ============================================================
// Kernel 4: merge 128 candidates -> top-4, then
// out[c,t] = 0.25 * sum_k P[c, idx_k] + b[c]
// grid T blocks, 128 threads.
// ============================================================
__global__ void merge_project_kernel(const float* __restrict__ bias,
                                     float* __restrict__ out) {
    __shared__ float sv[NSPLIT * CAND];
    __shared__ int   si[NSPLIT * CAND];
    __shared__ int   sel[KSEL];

    const int t   = blockIdx.x;
    const int tid = threadIdx.x;

    const int split = tid >> 6;        // 0..1
    const int slot  = tid & 63;
    const int base  = (split * T + t) * CAND + slot;
    sv[tid] = g_cand_val[base];
    si[tid] = g_cand_idx[base];
    __syncthreads();

    if (tid == 0) {
        // serial top-4 selection with jax tie-break (lower index wins on ties)
        for (int j = 0; j < KSEL; ++j) {
            float bv = NEG_INF;
            int   bi = 0x7fffffff;
            int   bp = 0;
            for (int i = 0; i < NSPLIT * CAND; ++i) {
                float v = sv[i];
                int  ix = si[i];
                if (v > bv || (v == bv && ix < bi)) { bv = v; bi = ix; bp = i; }
            }
            sel[j] = bi;
            sv[bp] = NEG_INF;
        }
    }
    __syncthreads();

    if (tid < C) {
        const float* Pr = g_P + tid * NREF;
        float o = 0.25f * (Pr[sel[0]] + Pr[sel[1]] + Pr[sel[2]] + Pr[sel[3]]);
        out[tid * T + t] = o + bias[tid];
    }
}

// ============================================================
extern "C" void kernel_launch(void* const* d_in, const int* in_sizes, int n_in,
                              void* d_out, int out_size) {
    const float* x    = (const float*)d_in[0];   // [1, 768, 8192]
    const float* lut  = (const float*)d_in[1];   // [1, 768, 16384]
    const float* w    = (const float*)d_in[2];   // [96, 768]
    const float* bias = (const float*)d_in[3];   // [96]
    float* out = (float*)d_out;                  // [1, 96, 8192]

    norm_kernel<<<NREF / 256, 256>>>(lut);
    proj_lut_kernel<<<dim3(NREF / 128, C / 4), 128>>>(lut, w);
    match_kernel<<<dim3(NSPLIT, T / TM), 256>>>(x, lut);
    merge_project_kernel<<<T, 128>>>(bias, out);
}

// round 11
// speedup vs baseline: 1.4180x; 1.4180x over previous
#include <cuda_runtime.h>
#include <cuda_bf16.h>
#include <cstdint>

// ---------------- problem constants ----------------
#define D     768
#define T     8192
#define NREF  16384
#define C     96

// ---------------- match-kernel tiling ----------------
#define TM_CTA   128
#define TN_SUB   128               // n-subtile width
#define NSPLIT   16                // grid.y; each CTA covers NREF/NSPLIT = 1024 n
#define SUBTILES 8                 // 1024 / 128
#define KC       64                // K elems per stage
#define NITER    (D / KC)          // 12
#define TTILES   (T / TM_CTA)      // 64
#define CANDS    (NSPLIT * 4)      // 64 candidates per token

#define NEG_INF (-3.402823466e38f)

// smem layout (bytes)
// [0, 131072)       : 2 fp32 stages: A(64k x 128t fp32, 512B rows, 32KB) + B at +32KB
// [131072, 229376)  : bf16 buffers Ah/Am/Al/Bh/Bm/Bl, 16KB each ([row][k], XOR swizzle)
// [229376, 229888)  : Sn (128 floats inv-norms)
// epilogue reuses fp32 staging as 128 x 129 float score buffer (66048 B)
#define SM_F32STG  65536u
#define SM_AH      131072u
#define SM_AM      147456u
#define SM_AL      163840u
#define SM_BH      180224u
#define SM_BM      196608u
#define SM_BL      212992u
#define SM_SN      229376u
#define SMEM_BYTES 229888u
#define BUF_STRIDE 129

// ---------------- device scratch (10.4 MB total; stays under lazy-load limit) ----
__device__ float g_inv_rnorm[NREF];                    // 64 KB
__device__ float g_P[(size_t)C * NREF];                // 6.3 MB
__device__ float g_cand_val[(size_t)T * CANDS];        // 2 MB
__device__ int   g_cand_idx[(size_t)T * CANDS];        // 2 MB

// ---------------- PTX helpers (sm_80-era, compute_100-safe) ----------------
__device__ __forceinline__ void cpasync16(uint32_t s, const void* g) {
    asm volatile("cp.async.cg.shared.global [%0], [%1], 16;"
                 :: "r"(s), "l"(g) : "memory");
}
__device__ __forceinline__ void cp_commit() {
    asm volatile("cp.async.commit_group;" ::: "memory");
}
template <int N>
__device__ __forceinline__ void cp_wait() {
    asm volatile("cp.async.wait_group %0;" :: "n"(N) : "memory");
}
__device__ __forceinline__ void ldsm4(uint32_t* r, uint32_t addr) {
    asm volatile("ldmatrix.sync.aligned.m8n8.x4.shared.b16 {%0,%1,%2,%3}, [%4];"
        : "=r"(r[0]), "=r"(r[1]), "=r"(r[2]), "=r"(r[3]) : "r"(addr));
}
__device__ __forceinline__ void ldsm2(uint32_t* r, uint32_t addr) {
    asm volatile("ldmatrix.sync.aligned.m8n8.x2.shared.b16 {%0,%1}, [%2];"
        : "=r"(r[0]), "=r"(r[1]) : "r"(addr));
}
__device__ __forceinline__ void mma_bf16(float* d, const uint32_t* a, const uint32_t* b) {
    asm volatile(
        "mma.sync.aligned.m16n8k16.row.col.f32.bf16.bf16.f32 "
        "{%0,%1,%2,%3}, {%4,%5,%6,%7}, {%8,%9}, {%0,%1,%2,%3};"
        : "+f"(d[0]), "+f"(d[1]), "+f"(d[2]), "+f"(d[3])
        : "r"(a[0]), "r"(a[1]), "r"(a[2]), "r"(a[3]), "r"(b[0]), "r"(b[1]));
}

// ============================================================
// Prologue 1: inverse L2 norms of lut columns (fp32)
// ============================================================
__global__ void norm_kernel(const float* __restrict__ lut) {
    int n = blockIdx.x * blockDim.x + threadIdx.x;
    float s = 0.f;
#pragma unroll 8
    for (int d = 0; d < D; ++d) {
        float v = lut[(size_t)d * NREF + n];
        s = fmaf(v, v, s);
    }
    g_inv_rnorm[n] = 1.0f / sqrtf(s);
}

// ============================================================
// Prologue 2: P = W @ lut  (96 x 16384), fp32, 8 channels/thread
// ============================================================
__global__ void proj_lut_kernel(const float* __restrict__ lut,
                                const float* __restrict__ w) {
    int n  = blockIdx.x * 128 + threadIdx.x;
    int c0 = blockIdx.y * 8;
    float a[8] = {0, 0, 0, 0, 0, 0, 0, 0};
#pragma unroll 4
    for (int d = 0; d < D; ++d) {
        float l = lut[(size_t)d * NREF + n];
#pragma unroll
        for (int c = 0; c < 8; ++c)
            a[c] = fmaf(w[(c0 + c) * D + d], l, a[c]);
    }
#pragma unroll
    for (int c = 0; c < 8; ++c)
        g_P[(size_t)(c0 + c) * NREF + n] = a[c];
}

// ============================================================
// top-4 helpers (strict >: earliest/lowest index wins ties, matching jax)
// ============================================================
__device__ __forceinline__ void insert4(float* v, int* ix, float s, int n) {
    if (s > v[3]) {
        if (s > v[0]) {
            v[3]=v[2]; ix[3]=ix[2]; v[2]=v[1]; ix[2]=ix[1];
            v[1]=v[0]; ix[1]=ix[0]; v[0]=s;    ix[0]=n;
        } else if (s > v[1]) {
            v[3]=v[2]; ix[3]=ix[2]; v[2]=v[1]; ix[2]=ix[1];
            v[1]=s;    ix[1]=n;
        } else if (s > v[2]) {
            v[3]=v[2]; ix[3]=ix[2]; v[2]=s; ix[2]=n;
        } else { v[3]=s; ix[3]=n; }
    }
}
__device__ __forceinline__ void insert4u(unsigned long long* v, unsigned long long k) {
    if (k > v[3]) {
        if (k > v[0])      { v[3]=v[2]; v[2]=v[1]; v[1]=v[0]; v[0]=k; }
        else if (k > v[1]) { v[3]=v[2]; v[2]=v[1]; v[1]=k; }
        else if (k > v[2]) { v[3]=v[2]; v[2]=k; }
        else               { v[3]=k; }
    }
}

// ============================================================
// Exact 3-way bf16 decomposition of an fp32 pair, packed bf16x2.
// x = h + m + l exactly (24 mantissa bits = 3 x 8).
// ============================================================
__device__ __forceinline__ void split3_pair(float f0, float f1,
                                            uint32_t& hu, uint32_t& mu, uint32_t& lu) {
    uint32_t h0 = __float_as_uint(f0) & 0xFFFF0000u;
    uint32_t h1 = __float_as_uint(f1) & 0xFFFF0000u;
    hu = __byte_perm(h0, h1, 0x7632);
    float r10 = f0 - __uint_as_float(h0);      // exact
    float r11 = f1 - __uint_as_float(h1);
    uint32_t m0 = __float_as_uint(r10) & 0xFFFF0000u;
    uint32_t m1 = __float_as_uint(r11) & 0xFFFF0000u;
    mu = __byte_perm(m0, m1, 0x7632);
    float r20 = r10 - __uint_as_float(m0);     // exact, <=8 significant bits
    float r21 = r11 - __uint_as_float(m1);
    lu = __byte_perm(__float_as_uint(r20), __float_as_uint(r21), 0x7632);
}

// ============================================================
// Main: in-kernel exact 3-way split + mma.sync 6-pass GEMM + running top-4.
// grid (TTILES=64, NSPLIT=16); 256 threads, 8 warps (2M x 4N), warp tile 64x32.
// ============================================================
__global__ __launch_bounds__(256, 1)
void match_kernel(const float* __restrict__ x, const float* __restrict__ lut) {
    extern __shared__ __align__(16) char smraw[];
    uint32_t smb;
    asm("{ .reg .u64 t; cvta.to.shared.u64 t, %1; cvt.u32.u64 %0, t; }"
        : "=r"(smb) : "l"(smraw));

    const int tid  = threadIdx.x;
    const int lane = tid & 31;
    const int wid  = tid >> 5;
    const int wm   = wid >> 2;       // 0..1
    const int wn   = wid & 3;        // 0..3
    const int t0   = blockIdx.x * TM_CTA;
    const int nb0  = blockIdx.y * (NREF / NSPLIT);

    // conversion mapping: token/row ct (0..127), k-half ch (0/1)
    const int ct = tid & 127;
    const int ch = tid >> 7;

    // ldmatrix lane mappings (hardware-validated in round 10)
    const int arow = lane & 15;
    const int akb  = lane >> 4;
    const int ar7  = arow & 7;
    const int brow = lane & 7;
    const int bkb  = (lane >> 3) & 1;
    const uint32_t aRowOff = (uint32_t)((wm * 64 + arow) * 128);
    const uint32_t bRowOff = (uint32_t)((wn * 32 + brow) * 128);

    float* Sn = (float*)(smraw + SM_SN);

    // running top-4 across all subtiles (owned by threads 0..127)
    float topv[4] = {NEG_INF, NEG_INF, NEG_INF, NEG_INF};
    int   topi[4] = {0, 0, 0, 0};

#pragma unroll 1
    for (int st = 0; st < SUBTILES; ++st) {
        const int nb = nb0 + st * TN_SUB;
        if (tid < TN_SUB) Sn[tid] = g_inv_rnorm[nb + tid];

        float acc[4][4][4];
#pragma unroll
        for (int mt = 0; mt < 4; ++mt)
#pragma unroll
            for (int nt = 0; nt < 4; ++nt)
#pragma unroll
                for (int q = 0; q < 4; ++q) acc[mt][nt][q] = 0.f;

        // ---- fp32 stage loader: A = x[kc*64.., t0..+128], B = lut[.., nb..+128]
        auto load_stage = [&](int kc) {
            const uint32_t dst = smb + (uint32_t)(kc & 1) * SM_F32STG;
            const int d0 = kc * KC;
            const float* xs = x   + (size_t)d0 * T    + t0;
            const float* ls = lut + (size_t)d0 * NREF + nb;
#pragma unroll
            for (int i = 0; i < 8; ++i) {
                const int id = tid + i * 256;
                const int r = id >> 5, cq = id & 31;
                cpasync16(dst + (uint32_t)(r * 512 + cq * 16),
                          xs + (size_t)r * T + cq * 4);
            }
#pragma unroll
            for (int i = 0; i < 8; ++i) {
                const int id = tid + i * 256;
                const int r = id >> 5, cq = id & 31;
                cpasync16(dst + 32768u + (uint32_t)(r * 512 + cq * 16),
                          ls + (size_t)r * NREF + cq * 4);
            }
            cp_commit();
        };

        load_stage(0);

#pragma unroll 1
        for (int kc = 0; kc < NITER; ++kc) {
            if (kc + 1 < NITER) { load_stage(kc + 1); cp_wait<1>(); }
            else                { cp_wait<0>(); }
            __syncthreads();   // fp32(kc) ready; prior mma done before bf16 overwrite

            // ---- exact split fp32 [k][row] -> bf16 h/m/l [row][k] (swizzled) ----
            {
                const float* Af = (const float*)(smraw + (size_t)(kc & 1) * SM_F32STG);
                const float* Bf = Af + 8192;   // +32KB
#pragma unroll 4
                for (int kp = 0; kp < 16; ++kp) {
                    const int k = ch * 32 + kp * 2;
                    const uint32_t pos = (uint32_t)(ct * 128 +
                        ((((k >> 3) ^ (ct & 7)) << 4)) + ((2 * k) & 15));
                    uint32_t hu, mu, lu;
                    split3_pair(Af[k * 128 + ct], Af[(k + 1) * 128 + ct], hu, mu, lu);
                    *(uint32_t*)(smraw + SM_AH + pos) = hu;
                    *(uint32_t*)(smraw + SM_AM + pos) = mu;
                    *(uint32_t*)(smraw + SM_AL + pos) = lu;
                    split3_pair(Bf[k * 128 + ct], Bf[(k + 1) * 128 + ct], hu, mu, lu);
                    *(uint32_t*)(smraw + SM_BH + pos) = hu;
                    *(uint32_t*)(smraw + SM_BM + pos) = mu;
                    *(uint32_t*)(smraw + SM_BL + pos) = lu;
                }
            }
            __syncthreads();   // bf16 ready

            // ---- 6-pass MMA: hh, hm, hl, mh, mm, lh ----
#pragma unroll
            for (int ks = 0; ks < 4; ++ks) {
                const uint32_t ac = (uint32_t)(((ks * 2 + akb) ^ ar7) * 16);
                const uint32_t bc = (uint32_t)(((ks * 2 + bkb) ^ brow) * 16);
                uint32_t a_op[4][4], b_op[4][2];

                // A = h : hh, hm, hl
#pragma unroll
                for (int mt = 0; mt < 4; ++mt)
                    ldsm4(a_op[mt], smb + SM_AH + aRowOff + mt * 2048 + ac);
#pragma unroll
                for (int nt = 0; nt < 4; ++nt)
                    ldsm2(b_op[nt], smb + SM_BH + bRowOff + nt * 1024 + bc);
#pragma unroll
                for (int mt = 0; mt < 4; ++mt)
#pragma unroll
                    for (int nt = 0; nt < 4; ++nt)
                        mma_bf16(acc[mt][nt], a_op[mt], b_op[nt]);
#pragma unroll
                for (int nt = 0; nt < 4; ++nt)
                    ldsm2(b_op[nt], smb + SM_BM + bRowOff + nt * 1024 + bc);
#pragma unroll
                for (int mt = 0; mt < 4; ++mt)
#pragma unroll
                    for (int nt = 0; nt < 4; ++nt)
                        mma_bf16(acc[mt][nt], a_op[mt], b_op[nt]);
#pragma unroll
                for (int nt = 0; nt < 4; ++nt)
                    ldsm2(b_op[nt], smb + SM_BL + bRowOff + nt * 1024 + bc);
#pragma unroll
                for (int mt = 0; mt < 4; ++mt)
#pragma unroll
                    for (int nt = 0; nt < 4; ++nt)
                        mma_bf16(acc[mt][nt], a_op[mt], b_op[nt]);

                // A = m : mh, mm
#pragma unroll
                for (int mt = 0; mt < 4; ++mt)
                    ldsm4(a_op[mt], smb + SM_AM + aRowOff + mt * 2048 + ac);
#pragma unroll
                for (int nt = 0; nt < 4; ++nt)
                    ldsm2(b_op[nt], smb + SM_BH + bRowOff + nt * 1024 + bc);
#pragma unroll
                for (int mt = 0; mt < 4; ++mt)
#pragma unroll
                    for (int nt = 0; nt < 4; ++nt)
                        mma_bf16(acc[mt][nt], a_op[mt], b_op[nt]);
#pragma unroll
                for (int nt = 0; nt < 4; ++nt)
                    ldsm2(b_op[nt], smb + SM_BM + bRowOff + nt * 1024 + bc);
#pragma unroll
                for (int mt = 0; mt < 4; ++mt)
#pragma unroll
                    for (int nt = 0; nt < 4; ++nt)
                        mma_bf16(acc[mt][nt], a_op[mt], b_op[nt]);

                // A = l : lh
#pragma unroll
                for (int mt = 0; mt < 4; ++mt)
                    ldsm4(a_op[mt], smb + SM_AL + aRowOff + mt * 2048 + ac);
#pragma unroll
                for (int nt = 0; nt < 4; ++nt)
                    ldsm2(b_op[nt], smb + SM_BH + bRowOff + nt * 1024 + bc);
#pragma unroll
                for (int mt = 0; mt < 4; ++mt)
#pragma unroll
                    for (int nt = 0; nt < 4; ++nt)
                        mma_bf16(acc[mt][nt], a_op[mt], b_op[nt]);
            }
        }

        // ---- subtile epilogue: scale + update running top-4 ----
        __syncthreads();                 // all MMA done; fp32 staging reusable
        float* buf = (float*)smraw;      // 128 x BUF_STRIDE floats
        const int r0 = wm * 64 + (lane >> 2);
        const int cb = wn * 32 + 2 * (lane & 3);
#pragma unroll
        for (int mt = 0; mt < 4; ++mt)
#pragma unroll
            for (int nt = 0; nt < 4; ++nt) {
                const int rr = r0 + mt * 16;
                const int cc = cb + nt * 8;
                const float s0 = Sn[cc], s1 = Sn[cc + 1];
                buf[rr * BUF_STRIDE + cc]           = acc[mt][nt][0] * s0;
                buf[rr * BUF_STRIDE + cc + 1]       = acc[mt][nt][1] * s1;
                buf[(rr + 8) * BUF_STRIDE + cc]     = acc[mt][nt][2] * s0;
                buf[(rr + 8) * BUF_STRIDE + cc + 1] = acc[mt][nt][3] * s1;
            }
        __syncthreads();

        if (tid < TM_CTA) {
            const float* row = buf + tid * BUF_STRIDE;
#pragma unroll 4
            for (int cc = 0; cc < TN_SUB; ++cc)
                insert4(topv, topi, row[cc], nb + cc);
        }
        __syncthreads();   // scan done before next subtile's cp.async overwrites
    }

    // ---- final: 4 candidates per (token, split) ----
    if (tid < TM_CTA) {
        const size_t base = ((size_t)(t0 + tid) * NSPLIT + blockIdx.y) * 4;
#pragma unroll
        for (int j = 0; j < 4; ++j) {
            g_cand_val[base + j] = topv[j];
            g_cand_idx[base + j] = topi[j];
        }
    }
}

// ============================================================
// Merge 64 candidates/token -> top-4 (warp per token, u64 keys),
// then out[c,t] = 0.25 * sum_k P[c, idx_k] + b[c].
// grid T/4 blocks, 128 threads.
// ============================================================
__global__ __launch_bounds__(128, 1)
void merge_project_kernel(const float* __restrict__ bias,
                          float* __restrict__ out) {
    __shared__ int sel[4][4];
    const int w = threadIdx.x >> 5, lane = threadIdx.x & 31;
    const int t = blockIdx.x * 4 + w;

    const float* vb = g_cand_val + (size_t)t * CANDS;
    const int*   ib = g_cand_idx + (size_t)t * CANDS;

    unsigned long long best[4] = {0, 0, 0, 0};
#pragma unroll
    for (int j = 0; j < CANDS / 32; ++j) {
        const int e = lane + j * 32;
        uint32_t u = __float_as_uint(vb[e]);
        u ^= (u & 0x80000000u) ? 0xFFFFFFFFu : 0x80000000u;
        unsigned long long key =
            ((unsigned long long)u << 32) | (uint32_t)(0x7FFFFFFF - ib[e]);
        insert4u(best, key);
    }
#pragma unroll
    for (int off = 16; off; off >>= 1) {
        unsigned long long o0 = __shfl_xor_sync(0xFFFFFFFFu, best[0], off);
        unsigned long long o1 = __shfl_xor_sync(0xFFFFFFFFu, best[1], off);
        unsigned long long o2 = __shfl_xor_sync(0xFFFFFFFFu, best[2], off);
        unsigned long long o3 = __shfl_xor_sync(0xFFFFFFFFu, best[3], off);
        insert4u(best, o0); insert4u(best, o1);
        insert4u(best, o2); insert4u(best, o3);
    }
    if (lane < 4) sel[w][lane] = 0x7FFFFFFF - (int)(uint32_t)best[lane];
    __syncthreads();

    for (int i = threadIdx.x; i < 4 * C; i += 128) {
        const int cch = i % C;
        const int tw  = i / C;
        const float* Pr = g_P + (size_t)cch * NREF;
        const int* s = sel[tw];
        float o = 0.25f * (Pr[s[0]] + Pr[s[1]] + Pr[s[2]] + Pr[s[3]]);
        out[(size_t)cch * T + (blockIdx.x * 4 + tw)] = o + bias[cch];
    }
}

// ============================================================
extern "C" void kernel_launch(void* const* d_in, const int* in_sizes, int n_in,
                              void* d_out, int out_size) {
    const float* x    = (const float*)d_in[0];   // [1, 768, 8192]
    const float* lut  = (const float*)d_in[1];   // [1, 768, 16384]
    const float* w    = (const float*)d_in[2];   // [96, 768]
    const float* bias = (const float*)d_in[3];   // [96]
    float* out = (float*)d_out;                  // [1, 96, 8192]

    cudaFuncSetAttribute(match_kernel,
                         cudaFuncAttributeMaxDynamicSharedMemorySize,
                         SMEM_BYTES);

    norm_kernel<<<NREF / 256, 256>>>(lut);
    proj_lut_kernel<<<dim3(NREF / 128, C / 8), 128>>>(lut, w);
    match_kernel<<<dim3(TTILES, NSPLIT), 256, SMEM_BYTES>>>(x, lut);
    merge_project_kernel<<<T / 4, 128>>>(bias, out);
}

// round 12
// speedup vs baseline: 1.6832x; 1.1870x over previous
#include <cuda_runtime.h>
#include <cuda_bf16.h>
#include <cstdint>

// ---------------- problem constants ----------------
#define D     768
#define T     8192
#define NREF  16384
#define C     96

// ---------------- match-kernel tiling ----------------
#define TM_CTA   128
#define TN_SUB   128               // n-subtile width
#define NSPLIT   16                // grid.y; each CTA covers NREF/NSPLIT = 1024 n
#define SUBTILES 8                 // 1024 / 128
#define KC       64                // K elems per stage
#define NITER    (D / KC)          // 12
#define TTILES   (T / TM_CTA)      // 64
#define CANDS    (NSPLIT * 4)      // 64 candidates per token

#define NEG_INF (-3.402823466e38f)

// smem layout (bytes)
// [0, 131072)       : 2 fp32 stages: A(64k x 128t fp32, 512B rows, 32KB) + B at +32KB
// [131072, 229376)  : bf16 buffers Ah/Am/Al/Bh/Bm/Bl, 16KB each ([row][k], XOR swizzle)
// [229376, 229888)  : Sn (128 floats inv-norms)
// epilogue reuses fp32 staging as 128 x 129 float score buffer (66048 B)
#define SM_F32STG  65536u
#define SM_AH      131072u
#define SM_AM      147456u
#define SM_AL      163840u
#define SM_BH      180224u
#define SM_BM      196608u
#define SM_BL      212992u
#define SM_SN      229376u
#define SMEM_BYTES 229888u
#define BUF_STRIDE 129

// ---------------- device scratch (10.4 MB total) ----------------
__device__ float g_inv_rnorm[NREF];                    // 64 KB
__device__ float g_P[(size_t)C * NREF];                // 6.3 MB
__device__ float g_cand_val[(size_t)T * CANDS];        // 2 MB
__device__ int   g_cand_idx[(size_t)T * CANDS];        // 2 MB

// ---------------- PTX helpers (sm_80-era, compute_100-safe) ----------------
__device__ __forceinline__ void cpasync16(uint32_t s, const void* g) {
    asm volatile("cp.async.cg.shared.global [%0], [%1], 16;"
                 :: "r"(s), "l"(g) : "memory");
}
__device__ __forceinline__ void cp_commit() {
    asm volatile("cp.async.commit_group;" ::: "memory");
}
template <int N>
__device__ __forceinline__ void cp_wait() {
    asm volatile("cp.async.wait_group %0;" :: "n"(N) : "memory");
}
__device__ __forceinline__ void ldsm4(uint32_t* r, uint32_t addr) {
    asm volatile("ldmatrix.sync.aligned.m8n8.x4.shared.b16 {%0,%1,%2,%3}, [%4];"
        : "=r"(r[0]), "=r"(r[1]), "=r"(r[2]), "=r"(r[3]) : "r"(addr));
}
__device__ __forceinline__ void ldsm2(uint32_t* r, uint32_t addr) {
    asm volatile("ldmatrix.sync.aligned.m8n8.x2.shared.b16 {%0,%1}, [%2];"
        : "=r"(r[0]), "=r"(r[1]) : "r"(addr));
}
__device__ __forceinline__ void mma_bf16(float* d, const uint32_t* a, const uint32_t* b) {
    asm volatile(
        "mma.sync.aligned.m16n8k16.row.col.f32.bf16.bf16.f32 "
        "{%0,%1,%2,%3}, {%4,%5,%6,%7}, {%8,%9}, {%0,%1,%2,%3};"
        : "+f"(d[0]), "+f"(d[1]), "+f"(d[2]), "+f"(d[3])
        : "r"(a[0]), "r"(a[1]), "r"(a[2]), "r"(a[3]), "r"(b[0]), "r"(b[1]));
}

// ============================================================
// Prologue 1: inverse L2 norms of lut columns (fp32)
// ============================================================
__global__ void norm_kernel(const float* __restrict__ lut) {
    int n = blockIdx.x * blockDim.x + threadIdx.x;
    float s = 0.f;
#pragma unroll 8
    for (int d = 0; d < D; ++d) {
        float v = lut[(size_t)d * NREF + n];
        s = fmaf(v, v, s);
    }
    g_inv_rnorm[n] = 1.0f / sqrtf(s);
}

// ============================================================
// Prologue 2: P = W @ lut  (96 x 16384), fp32, 8 channels/thread
// ============================================================
__global__ void proj_lut_kernel(const float* __restrict__ lut,
                                const float* __restrict__ w) {
    int n  = blockIdx.x * 128 + threadIdx.x;
    int c0 = blockIdx.y * 8;
    float a[8] = {0, 0, 0, 0, 0, 0, 0, 0};
#pragma unroll 4
    for (int d = 0; d < D; ++d) {
        float l = lut[(size_t)d * NREF + n];
#pragma unroll
        for (int c = 0; c < 8; ++c)
            a[c] = fmaf(w[(c0 + c) * D + d], l, a[c]);
    }
#pragma unroll
    for (int c = 0; c < 8; ++c)
        g_P[(size_t)(c0 + c) * NREF + n] = a[c];
}

// ============================================================
// top-4 helpers (strict >: earliest/lowest index wins ties, matching jax)
// ============================================================
__device__ __forceinline__ void insert4(float* v, int* ix, float s, int n) {
    if (s > v[3]) {
        if (s > v[0]) {
            v[3]=v[2]; ix[3]=ix[2]; v[2]=v[1]; ix[2]=ix[1];
            v[1]=v[0]; ix[1]=ix[0]; v[0]=s;    ix[0]=n;
        } else if (s > v[1]) {
            v[3]=v[2]; ix[3]=ix[2]; v[2]=v[1]; ix[2]=ix[1];
            v[1]=s;    ix[1]=n;
        } else if (s > v[2]) {
            v[3]=v[2]; ix[3]=ix[2]; v[2]=s; ix[2]=n;
        } else { v[3]=s; ix[3]=n; }
    }
}
__device__ __forceinline__ void insert4u(unsigned long long* v, unsigned long long k) {
    if (k > v[3]) {
        if (k > v[0])      { v[3]=v[2]; v[2]=v[1]; v[1]=v[0]; v[0]=k; }
        else if (k > v[1]) { v[3]=v[2]; v[2]=v[1]; v[1]=k; }
        else if (k > v[2]) { v[3]=v[2]; v[2]=k; }
        else               { v[3]=k; }
    }
}

// ============================================================
// Exact 3-way bf16 decomposition of an fp32 pair, packed bf16x2.
// x = h + m + l exactly (24 mantissa bits = 3 x 8).
// ============================================================
__device__ __forceinline__ void split3_pair(float f0, float f1,
                                            uint32_t& hu, uint32_t& mu, uint32_t& lu) {
    uint32_t h0 = __float_as_uint(f0) & 0xFFFF0000u;
    uint32_t h1 = __float_as_uint(f1) & 0xFFFF0000u;
    hu = __byte_perm(h0, h1, 0x7632);
    float r10 = f0 - __uint_as_float(h0);      // exact
    float r11 = f1 - __uint_as_float(h1);
    uint32_t m0 = __float_as_uint(r10) & 0xFFFF0000u;
    uint32_t m1 = __float_as_uint(r11) & 0xFFFF0000u;
    mu = __byte_perm(m0, m1, 0x7632);
    float r20 = r10 - __uint_as_float(m0);     // exact, <=8 significant bits
    float r21 = r11 - __uint_as_float(m1);
    lu = __byte_perm(__float_as_uint(r20), __float_as_uint(r21), 0x7632);
}

// ============================================================
// Main: in-kernel exact 3-way split + mma.sync 6-pass GEMM + running top-4.
// grid (TTILES=64, NSPLIT=16); 256 threads, 8 warps (2M x 4N), warp tile 64x32.
// This round: STS.128 conflict-free conversion writes; B operands
// register-cached per ks (loaded once, A reloaded per pass group).
// ============================================================
__global__ __launch_bounds__(256, 1)
void match_kernel(const float* __restrict__ x, const float* __restrict__ lut) {
    extern __shared__ __align__(16) char smraw[];
    uint32_t smb;
    asm("{ .reg .u64 t; cvta.to.shared.u64 t, %1; cvt.u32.u64 %0, t; }"
        : "=r"(smb) : "l"(smraw));

    const int tid  = threadIdx.x;
    const int lane = tid & 31;
    const int wid  = tid >> 5;
    const int wm   = wid >> 2;       // 0..1
    const int wn   = wid & 3;        // 0..3
    const int t0   = blockIdx.x * TM_CTA;
    const int nb0  = blockIdx.y * (NREF / NSPLIT);

    // conversion mapping: token/row ct (0..127), k-half ch (0/1)
    const int ct = tid & 127;
    const int ch = tid >> 7;

    // ldmatrix lane mappings (hardware-validated rounds 10-11)
    const int arow = lane & 15;
    const int akb  = lane >> 4;
    const int ar7  = arow & 7;
    const int brow = lane & 7;
    const int bkb  = (lane >> 3) & 1;
    const uint32_t aRowOff = (uint32_t)((wm * 64 + arow) * 128);
    const uint32_t bRowOff = (uint32_t)((wn * 32 + brow) * 128);

    float* Sn = (float*)(smraw + SM_SN);

    // running top-4 across all subtiles (owned by threads 0..127)
    float topv[4] = {NEG_INF, NEG_INF, NEG_INF, NEG_INF};
    int   topi[4] = {0, 0, 0, 0};

#pragma unroll 1
    for (int st = 0; st < SUBTILES; ++st) {
        const int nb = nb0 + st * TN_SUB;
        if (tid < TN_SUB) Sn[tid] = g_inv_rnorm[nb + tid];

        float acc[4][4][4];
#pragma unroll
        for (int mt = 0; mt < 4; ++mt)
#pragma unroll
            for (int nt = 0; nt < 4; ++nt)
#pragma unroll
                for (int q = 0; q < 4; ++q) acc[mt][nt][q] = 0.f;

        // ---- fp32 stage loader: A = x[kc*64.., t0..+128], B = lut[.., nb..+128]
        auto load_stage = [&](int kc) {
            const uint32_t dst = smb + (uint32_t)(kc & 1) * SM_F32STG;
            const int d0 = kc * KC;
            const float* xs = x   + (size_t)d0 * T    + t0;
            const float* ls = lut + (size_t)d0 * NREF + nb;
#pragma unroll
            for (int i = 0; i < 8; ++i) {
                const int id = tid + i * 256;
                const int r = id >> 5, cq = id & 31;
                cpasync16(dst + (uint32_t)(r * 512 + cq * 16),
                          xs + (size_t)r * T + cq * 4);
            }
#pragma unroll
            for (int i = 0; i < 8; ++i) {
                const int id = tid + i * 256;
                const int r = id >> 5, cq = id & 31;
                cpasync16(dst + 32768u + (uint32_t)(r * 512 + cq * 16),
                          ls + (size_t)r * NREF + cq * 4);
            }
            cp_commit();
        };

        load_stage(0);

#pragma unroll 1
        for (int kc = 0; kc < NITER; ++kc) {
            if (kc + 1 < NITER) { load_stage(kc + 1); cp_wait<1>(); }
            else                { cp_wait<0>(); }
            __syncthreads();   // fp32(kc) ready; prior mma done before bf16 overwrite

            // ---- exact split fp32 [k][row] -> bf16 h/m/l [row][k] (swizzled) ----
            // Chunked: 4 k-pairs -> one 16B STS.128 per buffer (conflict-free:
            // warp covers 32 distinct 128B rows, 4 lanes per 16B column = 4 phases).
            {
                const float* Af = (const float*)(smraw + (size_t)(kc & 1) * SM_F32STG);
                const float* Bf = Af + 8192;   // +32KB
#pragma unroll
                for (int cch = 0; cch < 4; ++cch) {
                    const int kbase = ch * 32 + cch * 8;       // 8 k values
                    const int q     = kbase >> 3;              // ch*4 + cch
                    const uint32_t pos = (uint32_t)(ct * 128 + ((q ^ (ct & 7)) << 4));
                    uint32_t h[4], m[4], l[4];
                    // A
#pragma unroll
                    for (int p = 0; p < 4; ++p) {
                        const int k = kbase + 2 * p;
                        split3_pair(Af[k * 128 + ct], Af[(k + 1) * 128 + ct],
                                    h[p], m[p], l[p]);
                    }
                    *(uint4*)(smraw + SM_AH + pos) = make_uint4(h[0], h[1], h[2], h[3]);
                    *(uint4*)(smraw + SM_AM + pos) = make_uint4(m[0], m[1], m[2], m[3]);
                    *(uint4*)(smraw + SM_AL + pos) = make_uint4(l[0], l[1], l[2], l[3]);
                    // B
#pragma unroll
                    for (int p = 0; p < 4; ++p) {
                        const int k = kbase + 2 * p;
                        split3_pair(Bf[k * 128 + ct], Bf[(k + 1) * 128 + ct],
                                    h[p], m[p], l[p]);
                    }
                    *(uint4*)(smraw + SM_BH + pos) = make_uint4(h[0], h[1], h[2], h[3]);
                    *(uint4*)(smraw + SM_BM + pos) = make_uint4(m[0], m[1], m[2], m[3]);
                    *(uint4*)(smraw + SM_BL + pos) = make_uint4(l[0], l[1], l[2], l[3]);
                }
            }
            __syncthreads();   // bf16 ready

            // ---- 6-pass MMA per ks: B h/m/l cached in registers ----
#pragma unroll
            for (int ks = 0; ks < 4; ++ks) {
                const uint32_t ac = (uint32_t)(((ks * 2 + akb) ^ ar7) * 16);
                const uint32_t bc = (uint32_t)(((ks * 2 + bkb) ^ brow) * 16);
                uint32_t a_op[4][4];
                uint32_t bh[4][2], bm[4][2], bl[4][2];

#pragma unroll
                for (int nt = 0; nt < 4; ++nt) {
                    ldsm2(bh[nt], smb + SM_BH + bRowOff + nt * 1024 + bc);
                    ldsm2(bm[nt], smb + SM_BM + bRowOff + nt * 1024 + bc);
                    ldsm2(bl[nt], smb + SM_BL + bRowOff + nt * 1024 + bc);
                }

                // A = h : hh, hm, hl
#pragma unroll
                for (int mt = 0; mt < 4; ++mt)
                    ldsm4(a_op[mt], smb + SM_AH + aRowOff + mt * 2048 + ac);
#pragma unroll
                for (int mt = 0; mt < 4; ++mt)
#pragma unroll
                    for (int nt = 0; nt < 4; ++nt)
                        mma_bf16(acc[mt][nt], a_op[mt], bh[nt]);
#pragma unroll
                for (int mt = 0; mt < 4; ++mt)
#pragma unroll
                    for (int nt = 0; nt < 4; ++nt)
                        mma_bf16(acc[mt][nt], a_op[mt], bm[nt]);
#pragma unroll
                for (int mt = 0; mt < 4; ++mt)
#pragma unroll
                    for (int nt = 0; nt < 4; ++nt)
                        mma_bf16(acc[mt][nt], a_op[mt], bl[nt]);

                // A = m : mh, mm
#pragma unroll
                for (int mt = 0; mt < 4; ++mt)
                    ldsm4(a_op[mt], smb + SM_AM + aRowOff + mt * 2048 + ac);
#pragma unroll
                for (int mt = 0; mt < 4; ++mt)
#pragma unroll
                    for (int nt = 0; nt < 4; ++nt)
                        mma_bf16(acc[mt][nt], a_op[mt], bh[nt]);
#pragma unroll
                for (int mt = 0; mt < 4; ++mt)
#pragma unroll
                    for (int nt = 0; nt < 4; ++nt)
                        mma_bf16(acc[mt][nt], a_op[mt], bm[nt]);

                // A = l : lh
#pragma unroll
                for (int mt = 0; mt < 4; ++mt)
                    ldsm4(a_op[mt], smb + SM_AL + aRowOff + mt * 2048 + ac);
#pragma unroll
                for (int mt = 0; mt < 4; ++mt)
#pragma unroll
                    for (int nt = 0; nt < 4; ++nt)
                        mma_bf16(acc[mt][nt], a_op[mt], bh[nt]);
            }
        }

        // ---- subtile epilogue: scale + update running top-4 ----
        __syncthreads();                 // all MMA done; fp32 staging reusable
        float* buf = (float*)smraw;      // 128 x BUF_STRIDE floats
        const int r0 = wm * 64 + (lane >> 2);
        const int cb = wn * 32 + 2 * (lane & 3);
#pragma unroll
        for (int mt = 0; mt < 4; ++mt)
#pragma unroll
            for (int nt = 0; nt < 4; ++nt) {
                const int rr = r0 + mt * 16;
                const int cc = cb + nt * 8;
                const float s0 = Sn[cc], s1 = Sn[cc + 1];
                buf[rr * BUF_STRIDE + cc]           = acc[mt][nt][0] * s0;
                buf[rr * BUF_STRIDE + cc + 1]       = acc[mt][nt][1] * s1;
                buf[(rr + 8) * BUF_STRIDE + cc]     = acc[mt][nt][2] * s0;
                buf[(rr + 8) * BUF_STRIDE + cc + 1] = acc[mt][nt][3] * s1;
            }
        __syncthreads();

        if (tid < TM_CTA) {
            const float* row = buf + tid * BUF_STRIDE;
#pragma unroll 4
            for (int cc = 0; cc < TN_SUB; ++cc)
                insert4(topv, topi, row[cc], nb + cc);
        }
        __syncthreads();   // scan done before next subtile's cp.async overwrites
    }

    // ---- final: 4 candidates per (token, split) ----
    if (tid < TM_CTA) {
        const size_t base = ((size_t)(t0 + tid) * NSPLIT + blockIdx.y) * 4;
#pragma unroll
        for (int j = 0; j < 4; ++j) {
            g_cand_val[base + j] = topv[j];
            g_cand_idx[base + j] = topi[j];
        }
    }
}

// ============================================================
// Merge 64 candidates/token -> top-4 (warp per token, u64 keys),
// then out[c,t] = 0.25 * sum_k P[c, idx_k] + b[c].
// grid T/4 blocks, 128 threads.
// ============================================================
__global__ __launch_bounds__(128, 1)
void merge_project_kernel(const float* __restrict__ bias,
                          float* __restrict__ out) {
    __shared__ int sel[4][4];
    const int w = threadIdx.x >> 5, lane = threadIdx.x & 31;
    const int t = blockIdx.x * 4 + w;

    const float* vb = g_cand_val + (size_t)t * CANDS;
    const int*   ib = g_cand_idx + (size_t)t * CANDS;

    unsigned long long best[4] = {0, 0, 0, 0};
#pragma unroll
    for (int j = 0; j < CANDS / 32; ++j) {
        const int e = lane + j * 32;
        uint32_t u = __float_as_uint(vb[e]);
        u ^= (u & 0x80000000u) ? 0xFFFFFFFFu : 0x80000000u;
        unsigned long long key =
            ((unsigned long long)u << 32) | (uint32_t)(0x7FFFFFFF - ib[e]);
        insert4u(best, key);
    }
#pragma unroll
    for (int off = 16; off; off >>= 1) {
        unsigned long long o0 = __shfl_xor_sync(0xFFFFFFFFu, best[0], off);
        unsigned long long o1 = __shfl_xor_sync(0xFFFFFFFFu, best[1], off);
        unsigned long long o2 = __shfl_xor_sync(0xFFFFFFFFu, best[2], off);
        unsigned long long o3 = __shfl_xor_sync(0xFFFFFFFFu, best[3], off);
        insert4u(best, o0); insert4u(best, o1);
        insert4u(best, o2); insert4u(best, o3);
    }
    if (lane < 4) sel[w][lane] = 0x7FFFFFFF - (int)(uint32_t)best[lane];
    __syncthreads();

    for (int i = threadIdx.x; i < 4 * C; i += 128) {
        const int cch = i % C;
        const int tw  = i / C;
        const float* Pr = g_P + (size_t)cch * NREF;
        const int* s = sel[tw];
        float o = 0.25f * (Pr[s[0]] + Pr[s[1]] + Pr[s[2]] + Pr[s[3]]);
        out[(size_t)cch * T + (blockIdx.x * 4 + tw)] = o + bias[cch];
    }
}

// ============================================================
extern "C" void kernel_launch(void* const* d_in, const int* in_sizes, int n_in,
                              void* d_out, int out_size) {
    const float* x    = (const float*)d_in[0];   // [1, 768, 8192]
    const float* lut  = (const float*)d_in[1];   // [1, 768, 16384]
    const float* w    = (const float*)d_in[2];   // [96, 768]
    const float* bias = (const float*)d_in[3];   // [96]
    float* out = (float*)d_out;                  // [1, 96, 8192]

    cudaFuncSetAttribute(match_kernel,
                         cudaFuncAttributeMaxDynamicSharedMemorySize,
                         SMEM_BYTES);

    norm_kernel<<<NREF / 256, 256>>>(lut);
    proj_lut_kernel<<<dim3(NREF / 128, C / 8), 128>>>(lut, w);
    match_kernel<<<dim3(TTILES, NSPLIT), 256, SMEM_BYTES>>>(x, lut);
    merge_project_kernel<<<T / 4, 128>>>(bias, out);
}